// round 1
// baseline (speedup 1.0000x reference)
#include <cuda_runtime.h>
#include <cstdint>

// Problem dims
#define KDIM 512    // in_features (reduction)
#define NDIM 512    // out_features
#define MDIM 1024   // batch
#define CDIM 128    // regions

// Tiling
#define BM 128
#define BN 128
#define BK 16
#define LDX 132     // padded smem row stride (floats) to reduce bank conflicts
#define LDW 132

__device__ __forceinline__ float tf32r(float x) {
    uint32_t r;
    asm("cvt.rna.tf32.f32 %0, %1;" : "=r"(r) : "f"(x));
    return __uint_as_float(r);
}

__device__ __forceinline__ void mma_tf32(float* c, const uint32_t* a, const uint32_t* b) {
    asm volatile(
        "mma.sync.aligned.m16n8k8.row.col.f32.tf32.tf32.f32 "
        "{%0,%1,%2,%3}, {%4,%5,%6,%7}, {%8,%9}, {%0,%1,%2,%3};\n"
        : "+f"(c[0]), "+f"(c[1]), "+f"(c[2]), "+f"(c[3])
        : "r"(a[0]), "r"(a[1]), "r"(a[2]), "r"(a[3]),
          "r"(b[0]), "r"(b[1]));
}

__global__ void __launch_bounds__(256, 2)
multilinear_tf32_kernel(const float* __restrict__ input,     // [KDIM, MDIM]
                        const int*   __restrict__ regions,   // [CDIM]
                        const float* __restrict__ wtab,      // [HEADS, KDIM, NDIM]
                        const float* __restrict__ btab,      // [HEADS, NDIM]
                        float*       __restrict__ out)       // [CDIM, MDIM, NDIM]
{
    __shared__ float Xs[BK][LDX];   // Xs[k][m] = input[k0+k][b0+m]
    __shared__ float Ws[BK][LDW];   // Ws[k][n] = W[k0+k][d0+n]
    __shared__ float Bs[BN];

    const int tid   = threadIdx.x;
    const int lane  = tid & 31;
    const int warp  = tid >> 5;
    const int warpM = warp >> 2;    // 0..1  -> 64 rows each
    const int warpN = warp & 3;     // 0..3  -> 32 cols each

    const int b0 = blockIdx.x * BM;
    const int d0 = blockIdx.y * BN;
    const int c  = blockIdx.z;
    const int head = regions[c];
    const float* __restrict__ W = wtab + (size_t)head * (KDIM * NDIM);

    if (tid < BN) Bs[tid] = btab[(size_t)head * NDIM + d0 + tid];

    // Global->smem load mapping: 16x128 tile = 512 float4; 256 threads x 2
    const int ldrow = tid >> 5;          // 0..7 (and +8)
    const int ldcol = (tid & 31) << 2;   // 0..124 step 4

    const float* xg = input + (size_t)ldrow * MDIM + b0 + ldcol;
    const float* wg = W     + (size_t)ldrow * NDIM + d0 + ldcol;

    float acc[4][4][4];
    #pragma unroll
    for (int i = 0; i < 4; i++)
        #pragma unroll
        for (int j = 0; j < 4; j++)
            #pragma unroll
            for (int r = 0; r < 4; r++) acc[i][j][r] = 0.0f;

    // Prologue: stage 0 (k0 = 0)
    float4 xr0 = *(const float4*)(xg);
    float4 xr1 = *(const float4*)(xg + 8 * MDIM);
    float4 wr0 = *(const float4*)(wg);
    float4 wr1 = *(const float4*)(wg + 8 * NDIM);

    {
        float* xp0 = &Xs[ldrow][ldcol];
        xp0[0] = tf32r(xr0.x); xp0[1] = tf32r(xr0.y); xp0[2] = tf32r(xr0.z); xp0[3] = tf32r(xr0.w);
        float* xp1 = &Xs[ldrow + 8][ldcol];
        xp1[0] = tf32r(xr1.x); xp1[1] = tf32r(xr1.y); xp1[2] = tf32r(xr1.z); xp1[3] = tf32r(xr1.w);
        float* wp0 = &Ws[ldrow][ldcol];
        wp0[0] = tf32r(wr0.x); wp0[1] = tf32r(wr0.y); wp0[2] = tf32r(wr0.z); wp0[3] = tf32r(wr0.w);
        float* wp1 = &Ws[ldrow + 8][ldcol];
        wp1[0] = tf32r(wr1.x); wp1[1] = tf32r(wr1.y); wp1[2] = tf32r(wr1.z); wp1[3] = tf32r(wr1.w);
    }
    __syncthreads();

    for (int k0 = 0; k0 < KDIM; k0 += BK) {
        const bool has_next = (k0 + BK) < KDIM;
        if (has_next) {
            const float* xgn = xg + (size_t)(k0 + BK) * MDIM;
            const float* wgn = wg + (size_t)(k0 + BK) * NDIM;
            xr0 = *(const float4*)(xgn);
            xr1 = *(const float4*)(xgn + 8 * MDIM);
            wr0 = *(const float4*)(wgn);
            wr1 = *(const float4*)(wgn + 8 * NDIM);
        }

        #pragma unroll
        for (int kk = 0; kk < BK; kk += 8) {
            uint32_t af[4][4];
            const int kA = kk + (lane & 3);
            #pragma unroll
            for (int mt = 0; mt < 4; mt++) {
                const int m = warpM * 64 + mt * 16 + (lane >> 2);
                af[mt][0] = __float_as_uint(Xs[kA][m]);
                af[mt][1] = __float_as_uint(Xs[kA][m + 8]);
                af[mt][2] = __float_as_uint(Xs[kA + 4][m]);
                af[mt][3] = __float_as_uint(Xs[kA + 4][m + 8]);
            }
            uint32_t bf[4][2];
            #pragma unroll
            for (int nt = 0; nt < 4; nt++) {
                const int n = warpN * 32 + nt * 8 + (lane >> 2);
                bf[nt][0] = __float_as_uint(Ws[kA][n]);
                bf[nt][1] = __float_as_uint(Ws[kA + 4][n]);
            }
            #pragma unroll
            for (int mt = 0; mt < 4; mt++)
                #pragma unroll
                for (int nt = 0; nt < 4; nt++)
                    mma_tf32(acc[mt][nt], af[mt], bf[nt]);
        }

        __syncthreads();
        if (has_next) {
            float* xp0 = &Xs[ldrow][ldcol];
            xp0[0] = tf32r(xr0.x); xp0[1] = tf32r(xr0.y); xp0[2] = tf32r(xr0.z); xp0[3] = tf32r(xr0.w);
            float* xp1 = &Xs[ldrow + 8][ldcol];
            xp1[0] = tf32r(xr1.x); xp1[1] = tf32r(xr1.y); xp1[2] = tf32r(xr1.z); xp1[3] = tf32r(xr1.w);
            float* wp0 = &Ws[ldrow][ldcol];
            wp0[0] = tf32r(wr0.x); wp0[1] = tf32r(wr0.y); wp0[2] = tf32r(wr0.z); wp0[3] = tf32r(wr0.w);
            float* wp1 = &Ws[ldrow + 8][ldcol];
            wp1[0] = tf32r(wr1.x); wp1[1] = tf32r(wr1.y); wp1[2] = tf32r(wr1.z); wp1[3] = tf32r(wr1.w);
            __syncthreads();
        }
    }

    // Epilogue: add bias, store float2 pairs
    float* outc = out + (size_t)c * MDIM * NDIM;
    #pragma unroll
    for (int mt = 0; mt < 4; mt++) {
        const int row = b0 + warpM * 64 + mt * 16 + (lane >> 2);
        #pragma unroll
        for (int nt = 0; nt < 4; nt++) {
            const int lcol = warpN * 32 + nt * 8 + 2 * (lane & 3);
            const int col  = d0 + lcol;
            const float bia0 = Bs[lcol];
            const float bia1 = Bs[lcol + 1];
            float2 v0 = make_float2(acc[mt][nt][0] + bia0, acc[mt][nt][1] + bia1);
            float2 v1 = make_float2(acc[mt][nt][2] + bia0, acc[mt][nt][3] + bia1);
            *(float2*)(outc + (size_t)row * NDIM + col)       = v0;
            *(float2*)(outc + (size_t)(row + 8) * NDIM + col) = v1;
        }
    }
}

extern "C" void kernel_launch(void* const* d_in, const int* in_sizes, int n_in,
                              void* d_out, int out_size) {
    const float* input   = (const float*)d_in[0];
    const int*   regions = (const int*)  d_in[1];
    const float* wtab    = (const float*)d_in[2];
    const float* btab    = (const float*)d_in[3];
    float* out = (float*)d_out;

    dim3 grid(MDIM / BM, NDIM / BN, CDIM);  // x fastest: b-tiles sharing W tile run adjacently -> L2 reuse
    multilinear_tf32_kernel<<<grid, 256>>>(input, regions, wtab, btab, out);
}

// round 4
// speedup vs baseline: 1.7399x; 1.7399x over previous
#include <cuda_runtime.h>
#include <cstdint>

#define KDIM 512
#define NDIM 512
#define MDIM 1024
#define CDIM 128

// ---------------- tcgen05 path tiling ----------------
#define BM 128
#define BN 128
#define BK 32
#define NSTAGES 16   // KDIM/BK
#define NCHUNK 4     // BN/32
#define KSTEPS 4     // BK/8  (tf32: K=8 per MMA)

#define TM_D   0     // 128 cols fp32 accumulator
#define TM_A0  128   // 32 cols stage buffer 0
#define TM_A1  160   // 32 cols stage buffer 1
#define TMEM_COLS_ALLOC 256

#define BSTAGE_BYTES 16384        // NCHUNK chunks * 32 n-rows * 128B (K-major rows)
#define EPI_STRIDE 68

// idesc kind::tf32: c=f32 (bit4), a=tf32 (2<<7), b=tf32 (2<<10),
// a_major=K (bit15=0), b_major=K (bit16=0), N=32 (4<<17), M=128 (8<<24)
#define IDESC ((1u<<4) | (2u<<7) | (2u<<10) | (4u<<17) | (8u<<24))

// K-major SW128 smem descriptor base (layout=SW128, version=1, SBO=64, LBO=1)
// == SMEM_DESC_BASE_SW128 from ptx_helpers (proven in test_mma.cu / test_2cta_mma_bf16.cu)
static constexpr uint64_t DESC_K =
    (uint64_t(2) << 61) | (uint64_t(1) << 46) | (uint64_t(64) << 32) | (uint64_t(1) << 16);

#define SWZ(x) ((x) ^ (((x) >> 3) & 0x70))

// Does this compilation pass support sm_103a-specific instructions?
#if defined(__CUDA_ARCH_FEAT_SM103_ALL) || \
    (defined(__CUDA_ARCH_SPECIFIC__) && (__CUDA_ARCH_SPECIFIC__ == 1030))
#define HAS_TCGEN05 1
#else
#define HAS_TCGEN05 0
#endif

// ---------------- common helpers ----------------
static __device__ __forceinline__ uint32_t smem_u32(const void* p) {
    uint32_t a;
    asm("{ .reg .u64 t; cvta.to.shared.u64 t, %1; cvt.u32.u64 %0, t; }" : "=r"(a) : "l"(p));
    return a;
}
static __device__ __forceinline__ uint32_t tf32_bits(float x) {
    uint32_t r; asm("cvt.rna.tf32.f32 %0, %1;" : "=r"(r) : "f"(x)); return r;
}
static __device__ __forceinline__ float tf32r(float x) {
    return __uint_as_float(tf32_bits(x));
}

#if HAS_TCGEN05
static __device__ __forceinline__ uint32_t elect1() {
    uint32_t p;
    asm volatile("{ .reg .pred p; elect.sync _|p, 0xFFFFFFFF; selp.b32 %0, 1, 0, p; }" : "=r"(p));
    return p;
}

#define TCGEN05_ALLOC(sa, n) \
    asm volatile("tcgen05.alloc.cta_group::1.sync.aligned.shared::cta.b32 [%0], %1;" \
                 :: "r"((uint32_t)(sa)), "r"((uint32_t)(n)) : "memory")
#define TCGEN05_RELINQ() \
    asm volatile("tcgen05.relinquish_alloc_permit.cta_group::1.sync.aligned;")
#define TCGEN05_DEALLOC(t, n) \
    asm volatile("tcgen05.dealloc.cta_group::1.sync.aligned.b32 %0, %1;" :: "r"(t), "r"((uint32_t)(n)))
#define TCGEN05_WAIT_ST() asm volatile("tcgen05.wait::st.sync.aligned;" ::: "memory")
#define TCGEN05_WAIT_LD() asm volatile("tcgen05.wait::ld.sync.aligned;" ::: "memory")
#define TCGEN05_FENCE_BEFORE() asm volatile("tcgen05.fence::before_thread_sync;" ::: "memory")
#define TCGEN05_FENCE_AFTER()  asm volatile("tcgen05.fence::after_thread_sync;" ::: "memory")
#define FENCE_PROXY() asm volatile("fence.proxy.async.shared::cta;" ::: "memory")
#define TCGEN05_COMMIT(mb) \
    asm volatile("tcgen05.commit.cta_group::1.mbarrier::arrive::one.shared::cluster.b64 [%0];" \
                 :: "r"((uint32_t)(mb)) : "memory")
#define MBAR_INIT(mb, n) \
    asm volatile("mbarrier.init.shared.b64 [%0], %1;" :: "r"((uint32_t)(mb)), "r"((uint32_t)(n)) : "memory")
#define MBAR_WAIT(mb, ph) do { \
    uint32_t _m = (uint32_t)(mb), _p = (uint32_t)(ph), _d; \
    asm volatile("{ .reg .pred p; mbarrier.try_wait.parity.acquire.cta.shared::cta.b64 p, [%1], %2; selp.b32 %0, 1, 0, p; }" \
                 : "=r"(_d) : "r"(_m), "r"(_p) : "memory"); \
    if (!_d) { \
        asm volatile("{ .reg .pred P1; WL_%=: mbarrier.try_wait.parity.acquire.cta.shared::cta.b64 P1, [%0], %1, 0x989680; @P1 bra.uni WD_%=; bra.uni WL_%=; WD_%=: }" \
                     :: "r"(_m), "r"(_p) : "memory"); \
    } } while (0)

#define TCGEN05_ST_X32(ta, r) \
    asm volatile("tcgen05.st.sync.aligned.32x32b.x32.b32 [%0], " \
        "{%1,%2,%3,%4,%5,%6,%7,%8,%9,%10,%11,%12,%13,%14,%15,%16," \
        "%17,%18,%19,%20,%21,%22,%23,%24,%25,%26,%27,%28,%29,%30,%31,%32};" \
        :: "r"(ta), \
        "r"((r)[0]),"r"((r)[1]),"r"((r)[2]),"r"((r)[3]),"r"((r)[4]),"r"((r)[5]),"r"((r)[6]),"r"((r)[7]), \
        "r"((r)[8]),"r"((r)[9]),"r"((r)[10]),"r"((r)[11]),"r"((r)[12]),"r"((r)[13]),"r"((r)[14]),"r"((r)[15]), \
        "r"((r)[16]),"r"((r)[17]),"r"((r)[18]),"r"((r)[19]),"r"((r)[20]),"r"((r)[21]),"r"((r)[22]),"r"((r)[23]), \
        "r"((r)[24]),"r"((r)[25]),"r"((r)[26]),"r"((r)[27]),"r"((r)[28]),"r"((r)[29]),"r"((r)[30]),"r"((r)[31]) \
        : "memory")

#define TCGEN05_LD_X32(r, ta) \
    asm volatile("tcgen05.ld.sync.aligned.32x32b.x32.b32 " \
        "{%0,%1,%2,%3,%4,%5,%6,%7,%8,%9,%10,%11,%12,%13,%14,%15," \
        "%16,%17,%18,%19,%20,%21,%22,%23,%24,%25,%26,%27,%28,%29,%30,%31}, [%32];" \
        : "=r"((r)[0]),"=r"((r)[1]),"=r"((r)[2]),"=r"((r)[3]),"=r"((r)[4]),"=r"((r)[5]),"=r"((r)[6]),"=r"((r)[7]), \
          "=r"((r)[8]),"=r"((r)[9]),"=r"((r)[10]),"=r"((r)[11]),"=r"((r)[12]),"=r"((r)[13]),"=r"((r)[14]),"=r"((r)[15]), \
          "=r"((r)[16]),"=r"((r)[17]),"=r"((r)[18]),"=r"((r)[19]),"=r"((r)[20]),"=r"((r)[21]),"=r"((r)[22]),"=r"((r)[23]), \
          "=r"((r)[24]),"=r"((r)[25]),"=r"((r)[26]),"=r"((r)[27]),"=r"((r)[28]),"=r"((r)[29]),"=r"((r)[30]),"=r"((r)[31]) \
        : "r"(ta))

static __device__ __forceinline__ void mma_tf32_ts(uint32_t d_tmem, uint32_t a_tmem,
                                                   uint64_t b_desc, uint32_t idesc, bool en) {
    uint32_t e = en ? 1u : 0u;
    asm volatile(
        "{\n\t.reg .pred p;\n\tsetp.ne.u32 p, %4, 0;\n\t"
        "tcgen05.mma.cta_group::1.kind::tf32 [%0], [%1], %2, %3, {%5,%5,%5,%5}, p;\n\t}"
        :: "r"(d_tmem), "r"(a_tmem), "l"(b_desc), "r"(idesc), "r"(e), "r"(0u)
        : "memory");
}
#endif  // HAS_TCGEN05

// ---------------- fallback (mma.sync tf32) helper ----------------
static __device__ __forceinline__ void mma_tf32_legacy(float* c, const uint32_t* a, const uint32_t* b) {
    asm volatile(
        "mma.sync.aligned.m16n8k8.row.col.f32.tf32.tf32.f32 "
        "{%0,%1,%2,%3}, {%4,%5,%6,%7}, {%8,%9}, {%0,%1,%2,%3};\n"
        : "+f"(c[0]), "+f"(c[1]), "+f"(c[2]), "+f"(c[3])
        : "r"(a[0]), "r"(a[1]), "r"(a[2]), "r"(a[3]), "r"(b[0]), "r"(b[1]));
}

__global__ void __launch_bounds__(256, 2)
ml_kernel(const float* __restrict__ input,    // [KDIM, MDIM]
          const int*   __restrict__ regions,  // [CDIM]
          const float* __restrict__ wtab,     // [HEADS, KDIM, NDIM]
          const float* __restrict__ btab,     // [HEADS, NDIM]
          float*       __restrict__ out)      // [CDIM, MDIM, NDIM]
{
#if HAS_TCGEN05
    // ================= tcgen05 TS-mode TF32, B K-major =================
    struct __align__(1024) SmemLayout {
        unsigned char buf[128 * EPI_STRIDE * 4];   // 34816 >= 2*BSTAGE_BYTES
        uint64_t mbar[2];
        uint32_t tmem_ptr;
    };
    __shared__ SmemLayout sm;

    const int tid  = threadIdx.x;
    const int warp = tid >> 5;
    const int lane = tid & 31;

    const int b0 = blockIdx.x * BM;
    const int d0 = blockIdx.y * BN;
    const int c  = blockIdx.z;
    const int head = regions[c];
    const float* __restrict__ W = wtab + (size_t)head * (KDIM * NDIM);

    const uint32_t smemB = smem_u32(sm.buf);
    const uint32_t mb0 = smem_u32(&sm.mbar[0]);
    const uint32_t mb1 = smem_u32(&sm.mbar[1]);

    if (warp == 0) {
        TCGEN05_ALLOC(smem_u32(&sm.tmem_ptr), TMEM_COLS_ALLOC);
        TCGEN05_RELINQ();
    }
    if (tid == 0) { MBAR_INIT(mb0, 1); MBAR_INIT(mb1, 1); }
    __syncthreads();
    uint32_t tmem_base;
    asm volatile("ld.shared.b32 %0, [%1];" : "=r"(tmem_base) : "r"(smem_u32(&sm.tmem_ptr)));

    auto load_stage = [&](int s, int bsel) {
        if (warp < 4) {
            // A: lane = m row (TMEM lane); 32 coalesced-across-warp LDG along k
            const float* ap = input + (size_t)(s * BK) * MDIM + b0 + warp * 32 + lane;
            uint32_t a[32];
            #pragma unroll
            for (int j = 0; j < 32; j++) a[j] = tf32_bits(__ldg(ap + (size_t)j * MDIM));
            uint32_t dst = tmem_base + (bsel ? TM_A1 : TM_A0) + ((uint32_t)warp << 21);
            TCGEN05_ST_X32(dst, a);
            TCGEN05_WAIT_ST();
            TCGEN05_FENCE_BEFORE();
        } else {
            // B: K-MAJOR rows. chunk ch = 32 n-rows x 128B (32 tf32 k values), SW128.
            // Register 4x4 transpose: gmem W[k][n] (n-contig) -> smem rows n (k-contig).
            const int ch = warp - 4;
            const int nq = lane >> 2;   // 0..7 : n-quad
            const int cc = lane & 3;    // 0..3 : k-quad low
            unsigned char* bbase = sm.buf + (size_t)bsel * BSTAGE_BYTES + ch * 4096;
            const float* wbase = W + (size_t)(s * BK) * NDIM + d0 + ch * 32;
            #pragma unroll
            for (int p = 0; p < 2; p++) {
                const int kq = cc + 4 * p;  // 0..7 : k-quad
                float4 v0 = *(const float4*)(wbase + (size_t)(kq * 4 + 0) * NDIM + nq * 4);
                float4 v1 = *(const float4*)(wbase + (size_t)(kq * 4 + 1) * NDIM + nq * 4);
                float4 v2 = *(const float4*)(wbase + (size_t)(kq * 4 + 2) * NDIM + nq * 4);
                float4 v3 = *(const float4*)(wbase + (size_t)(kq * 4 + 3) * NDIM + nq * 4);
                const float* f0 = (const float*)&v0;
                const float* f1 = (const float*)&v1;
                const float* f2 = (const float*)&v2;
                const float* f3 = (const float*)&v3;
                #pragma unroll
                for (int j = 0; j < 4; j++) {
                    uint4 t;
                    t.x = tf32_bits(f0[j]); t.y = tf32_bits(f1[j]);
                    t.z = tf32_bits(f2[j]); t.w = tf32_bits(f3[j]);
                    uint32_t off = SWZ((uint32_t)((nq * 4 + j) * 128 + kq * 16));
                    *(uint4*)(bbase + off) = t;
                }
            }
            FENCE_PROXY();
        }
    };

    load_stage(0, 0);
    __syncthreads();

    int ph0 = 0, ph1 = 0;
    for (int s = 0; s < NSTAGES; s++) {
        const int bsel = s & 1;
        if (warp == 0) {
            TCGEN05_FENCE_AFTER();
            if (elect1()) {
                const uint32_t abase = tmem_base + (bsel ? TM_A1 : TM_A0);
                #pragma unroll
                for (int ch = 0; ch < NCHUNK; ch++) {
                    const uint32_t baddr = smemB + bsel * BSTAGE_BYTES + ch * 4096;
                    const uint64_t bd0 = DESC_K | ((uint64_t)(baddr >> 4) & 0x3FFF);
                    #pragma unroll
                    for (int ks = 0; ks < KSTEPS; ks++) {
                        // K-step: 8 tf32 = 32B = +2 desc units (proven stepping)
                        mma_tf32_ts(tmem_base + TM_D + ch * 32, abase + ks * 8,
                                    bd0 + ks * 2, IDESC, !(s == 0 && ks == 0));
                    }
                }
                TCGEN05_COMMIT(bsel ? mb1 : mb0);
            }
        }
        if (s + 1 < NSTAGES) {
            const int nb = bsel ^ 1;
            if (s >= 1) {
                if (nb == 0) { MBAR_WAIT(mb0, ph0); ph0 ^= 1; }
                else         { MBAR_WAIT(mb1, ph1); ph1 ^= 1; }
            }
            load_stage(s + 1, nb);
        }
        __syncthreads();
    }
    // Last outstanding commit: stage 15 (bsel=1) -> mb1.
    MBAR_WAIT(mb1, ph1);
    TCGEN05_FENCE_AFTER();

    float* outc = out + (size_t)c * (MDIM * NDIM);
    const float* brow = btab + (size_t)head * NDIM + d0;
    float* eb = (float*)sm.buf;

    for (int h = 0; h < 2; h++) {
        __syncthreads();
        if (warp < 4) {
            uint32_t r[64];
            TCGEN05_LD_X32(r,      tmem_base + TM_D + h * 64);
            TCGEN05_LD_X32(r + 32, tmem_base + TM_D + h * 64 + 32);
            TCGEN05_WAIT_LD();
            float* rowp = eb + (warp * 32 + lane) * EPI_STRIDE;
            #pragma unroll
            for (int j = 0; j < 16; j++) {
                float4 v;
                v.x = __uint_as_float(r[j * 4 + 0]);
                v.y = __uint_as_float(r[j * 4 + 1]);
                v.z = __uint_as_float(r[j * 4 + 2]);
                v.w = __uint_as_float(r[j * 4 + 3]);
                *(float4*)(rowp + j * 4) = v;
            }
        }
        __syncthreads();
        #pragma unroll
        for (int it = 0; it < 8; it++) {
            const int e = it * 256 + tid;
            const int m = e >> 4;
            const int jj = (e & 15) << 2;
            float4 v = *(float4*)(eb + m * EPI_STRIDE + jj);
            float4 bv = *(const float4*)(brow + h * 64 + jj);
            v.x += bv.x; v.y += bv.y; v.z += bv.z; v.w += bv.w;
            *(float4*)(outc + (size_t)(b0 + m) * NDIM + d0 + h * 64 + jj) = v;
        }
    }

    __syncthreads();
    if (warp == 0) TCGEN05_DEALLOC(tmem_base, TMEM_COLS_ALLOC);

#else
    // ================= fallback: legacy mma.sync TF32 (round-1, 555us) =================
    #define BKF 16
    #define LDX 132
    __shared__ float Xs[BKF][LDX];
    __shared__ float Ws[BKF][LDX];
    __shared__ float Bs[BN];

    const int tid   = threadIdx.x;
    const int lane  = tid & 31;
    const int warp  = tid >> 5;
    const int warpM = warp >> 2;
    const int warpN = warp & 3;

    const int b0 = blockIdx.x * BM;
    const int d0 = blockIdx.y * BN;
    const int c  = blockIdx.z;
    const int head = regions[c];
    const float* __restrict__ W = wtab + (size_t)head * (KDIM * NDIM);

    if (tid < BN) Bs[tid] = btab[(size_t)head * NDIM + d0 + tid];

    const int ldrow = tid >> 5;
    const int ldcol = (tid & 31) << 2;

    const float* xg = input + (size_t)ldrow * MDIM + b0 + ldcol;
    const float* wg = W     + (size_t)ldrow * NDIM + d0 + ldcol;

    float acc[4][4][4];
    #pragma unroll
    for (int i = 0; i < 4; i++)
        #pragma unroll
        for (int j = 0; j < 4; j++)
            #pragma unroll
            for (int r = 0; r < 4; r++) acc[i][j][r] = 0.0f;

    float4 xr0 = *(const float4*)(xg);
    float4 xr1 = *(const float4*)(xg + 8 * MDIM);
    float4 wr0 = *(const float4*)(wg);
    float4 wr1 = *(const float4*)(wg + 8 * NDIM);
    {
        float* xp0 = &Xs[ldrow][ldcol];
        xp0[0]=tf32r(xr0.x); xp0[1]=tf32r(xr0.y); xp0[2]=tf32r(xr0.z); xp0[3]=tf32r(xr0.w);
        float* xp1 = &Xs[ldrow + 8][ldcol];
        xp1[0]=tf32r(xr1.x); xp1[1]=tf32r(xr1.y); xp1[2]=tf32r(xr1.z); xp1[3]=tf32r(xr1.w);
        float* wp0 = &Ws[ldrow][ldcol];
        wp0[0]=tf32r(wr0.x); wp0[1]=tf32r(wr0.y); wp0[2]=tf32r(wr0.z); wp0[3]=tf32r(wr0.w);
        float* wp1 = &Ws[ldrow + 8][ldcol];
        wp1[0]=tf32r(wr1.x); wp1[1]=tf32r(wr1.y); wp1[2]=tf32r(wr1.z); wp1[3]=tf32r(wr1.w);
    }
    __syncthreads();

    for (int k0 = 0; k0 < KDIM; k0 += BKF) {
        const bool has_next = (k0 + BKF) < KDIM;
        if (has_next) {
            const float* xgn = xg + (size_t)(k0 + BKF) * MDIM;
            const float* wgn = wg + (size_t)(k0 + BKF) * NDIM;
            xr0 = *(const float4*)(xgn);
            xr1 = *(const float4*)(xgn + 8 * MDIM);
            wr0 = *(const float4*)(wgn);
            wr1 = *(const float4*)(wgn + 8 * NDIM);
        }
        #pragma unroll
        for (int kk = 0; kk < BKF; kk += 8) {
            uint32_t af[4][4];
            const int kA = kk + (lane & 3);
            #pragma unroll
            for (int mt = 0; mt < 4; mt++) {
                const int m = warpM * 64 + mt * 16 + (lane >> 2);
                af[mt][0] = __float_as_uint(Xs[kA][m]);
                af[mt][1] = __float_as_uint(Xs[kA][m + 8]);
                af[mt][2] = __float_as_uint(Xs[kA + 4][m]);
                af[mt][3] = __float_as_uint(Xs[kA + 4][m + 8]);
            }
            uint32_t bf[4][2];
            #pragma unroll
            for (int nt = 0; nt < 4; nt++) {
                const int n = warpN * 32 + nt * 8 + (lane >> 2);
                bf[nt][0] = __float_as_uint(Ws[kA][n]);
                bf[nt][1] = __float_as_uint(Ws[kA + 4][n]);
            }
            #pragma unroll
            for (int mt = 0; mt < 4; mt++)
                #pragma unroll
                for (int nt = 0; nt < 4; nt++)
                    mma_tf32_legacy(acc[mt][nt], af[mt], bf[nt]);
        }
        __syncthreads();
        if (has_next) {
            float* xp0 = &Xs[ldrow][ldcol];
            xp0[0]=tf32r(xr0.x); xp0[1]=tf32r(xr0.y); xp0[2]=tf32r(xr0.z); xp0[3]=tf32r(xr0.w);
            float* xp1 = &Xs[ldrow + 8][ldcol];
            xp1[0]=tf32r(xr1.x); xp1[1]=tf32r(xr1.y); xp1[2]=tf32r(xr1.z); xp1[3]=tf32r(xr1.w);
            float* wp0 = &Ws[ldrow][ldcol];
            wp0[0]=tf32r(wr0.x); wp0[1]=tf32r(wr0.y); wp0[2]=tf32r(wr0.z); wp0[3]=tf32r(wr0.w);
            float* wp1 = &Ws[ldrow + 8][ldcol];
            wp1[0]=tf32r(wr1.x); wp1[1]=tf32r(wr1.y); wp1[2]=tf32r(wr1.z); wp1[3]=tf32r(wr1.w);
            __syncthreads();
        }
    }

    float* outc = out + (size_t)c * MDIM * NDIM;
    #pragma unroll
    for (int mt = 0; mt < 4; mt++) {
        const int row = b0 + warpM * 64 + mt * 16 + (lane >> 2);
        #pragma unroll
        for (int nt = 0; nt < 4; nt++) {
            const int lcol = warpN * 32 + nt * 8 + 2 * (lane & 3);
            const int col  = d0 + lcol;
            const float bia0 = Bs[lcol];
            const float bia1 = Bs[lcol + 1];
            float2 v0 = make_float2(acc[mt][nt][0] + bia0, acc[mt][nt][1] + bia1);
            float2 v1 = make_float2(acc[mt][nt][2] + bia0, acc[mt][nt][3] + bia1);
            *(float2*)(outc + (size_t)row * NDIM + col)       = v0;
            *(float2*)(outc + (size_t)(row + 8) * NDIM + col) = v1;
        }
    }
#endif
}

extern "C" void kernel_launch(void* const* d_in, const int* in_sizes, int n_in,
                              void* d_out, int out_size) {
    const float* input   = (const float*)d_in[0];
    const int*   regions = (const int*)  d_in[1];
    const float* wtab    = (const float*)d_in[2];
    const float* btab    = (const float*)d_in[3];
    float* out = (float*)d_out;

    dim3 grid(MDIM / BM, NDIM / BN, CDIM);
    ml_kernel<<<grid, 256>>>(input, regions, wtab, btab, out);
}

// round 16
// speedup vs baseline: 1.9658x; 1.1298x over previous
#include <cuda_runtime.h>
#include <cstdint>

#define KDIM 512
#define NDIM 512
#define MDIM 1024
#define CDIM 128

#define BM 128
#define BN 128
#define BK 32
#define NSTAGES 16   // KDIM/BK
#define STAGES 4     // ring depth
#define NCHUNK 4     // BN/32 (proven N=32 MMA chunks)
#define KSTEPS 4     // BK/8 (tf32 K=8 per MMA)
#define THREADS 288  // warp0=MMA, warps1-4=A, warps5-8=B

#define TM_D   0       // 128 cols fp32 accumulator
#define TM_A0  128     // 4 stage buffers x 32 cols = cols 128..255
#define TMEM_COLS_ALLOC 256

#define BSTG 16384     // one B stage: 128 rows x 128B (K-major SW128)
#define EPI_STRIDE 68
#define SMEM_DYN (STAGES * BSTG + 1024)

// idesc kind::tf32 (PROVEN in round 4): c=f32(bit4), a=tf32(2<<7), b=tf32(2<<10),
// N=32(4<<17), M=128(8<<24)
#define IDESC ((1u<<4) | (2u<<7) | (2u<<10) | (4u<<17) | (8u<<24))

// K-major SW128 descriptor base (proven): layout=SW128, ver=1, SBO=64, LBO=1
static constexpr uint64_t DESC_K =
    (uint64_t(2) << 61) | (uint64_t(1) << 46) | (uint64_t(64) << 32) | (uint64_t(1) << 16);

#define SWZ(x) ((x) ^ (((x) >> 3) & 0x70))

#if defined(__CUDA_ARCH_FEAT_SM103_ALL) || \
    (defined(__CUDA_ARCH_SPECIFIC__) && (__CUDA_ARCH_SPECIFIC__ == 1030))
#define HAS_TCGEN05 1
#else
#define HAS_TCGEN05 0
#endif

static __device__ __forceinline__ uint32_t smem_u32(const void* p) {
    uint32_t a;
    asm("{ .reg .u64 t; cvta.to.shared.u64 t, %1; cvt.u32.u64 %0, t; }" : "=r"(a) : "l"(p));
    return a;
}
static __device__ __forceinline__ uint32_t tf32_bits(float x) {
    uint32_t r; asm("cvt.rna.tf32.f32 %0, %1;" : "=r"(r) : "f"(x)); return r;
}

#if HAS_TCGEN05
static __device__ __forceinline__ uint32_t elect1() {
    uint32_t p;
    asm volatile("{ .reg .pred p; elect.sync _|p, 0xFFFFFFFF; selp.b32 %0, 1, 0, p; }" : "=r"(p));
    return p;
}

#define TCGEN05_ALLOC(sa, n) \
    asm volatile("tcgen05.alloc.cta_group::1.sync.aligned.shared::cta.b32 [%0], %1;" \
                 :: "r"((uint32_t)(sa)), "r"((uint32_t)(n)) : "memory")
#define TCGEN05_RELINQ() \
    asm volatile("tcgen05.relinquish_alloc_permit.cta_group::1.sync.aligned;")
#define TCGEN05_DEALLOC(t, n) \
    asm volatile("tcgen05.dealloc.cta_group::1.sync.aligned.b32 %0, %1;" :: "r"(t), "r"((uint32_t)(n)))
#define TCGEN05_WAIT_ST() asm volatile("tcgen05.wait::st.sync.aligned;" ::: "memory")
#define TCGEN05_WAIT_LD() asm volatile("tcgen05.wait::ld.sync.aligned;" ::: "memory")
#define TCGEN05_FENCE_BEFORE() asm volatile("tcgen05.fence::before_thread_sync;" ::: "memory")
#define TCGEN05_FENCE_AFTER()  asm volatile("tcgen05.fence::after_thread_sync;" ::: "memory")
#define FENCE_PROXY() asm volatile("fence.proxy.async.shared::cta;" ::: "memory")
#define TCGEN05_COMMIT(mb) \
    asm volatile("tcgen05.commit.cta_group::1.mbarrier::arrive::one.shared::cluster.b64 [%0];" \
                 :: "r"((uint32_t)(mb)) : "memory")
#define MBAR_INIT(mb, n) \
    asm volatile("mbarrier.init.shared.b64 [%0], %1;" :: "r"((uint32_t)(mb)), "r"((uint32_t)(n)) : "memory")
#define MBAR_ARRIVE(mb) \
    asm volatile("mbarrier.arrive.shared.b64 _, [%0];" :: "r"((uint32_t)(mb)) : "memory")
#define MBAR_WAIT(mb, ph) do { \
    uint32_t _m = (uint32_t)(mb), _p = (uint32_t)(ph), _d; \
    asm volatile("{ .reg .pred p; mbarrier.try_wait.parity.acquire.cta.shared::cta.b64 p, [%1], %2; selp.b32 %0, 1, 0, p; }" \
                 : "=r"(_d) : "r"(_m), "r"(_p) : "memory"); \
    if (!_d) { \
        asm volatile("{ .reg .pred P1; WL_%=: mbarrier.try_wait.parity.acquire.cta.shared::cta.b64 P1, [%0], %1, 0x989680; @P1 bra.uni WD_%=; bra.uni WL_%=; WD_%=: }" \
                     :: "r"(_m), "r"(_p) : "memory"); \
    } } while (0)

#define TCGEN05_ST_X32(ta, r) \
    asm volatile("tcgen05.st.sync.aligned.32x32b.x32.b32 [%0], " \
        "{%1,%2,%3,%4,%5,%6,%7,%8,%9,%10,%11,%12,%13,%14,%15,%16," \
        "%17,%18,%19,%20,%21,%22,%23,%24,%25,%26,%27,%28,%29,%30,%31,%32};" \
        :: "r"(ta), \
        "r"((r)[0]),"r"((r)[1]),"r"((r)[2]),"r"((r)[3]),"r"((r)[4]),"r"((r)[5]),"r"((r)[6]),"r"((r)[7]), \
        "r"((r)[8]),"r"((r)[9]),"r"((r)[10]),"r"((r)[11]),"r"((r)[12]),"r"((r)[13]),"r"((r)[14]),"r"((r)[15]), \
        "r"((r)[16]),"r"((r)[17]),"r"((r)[18]),"r"((r)[19]),"r"((r)[20]),"r"((r)[21]),"r"((r)[22]),"r"((r)[23]), \
        "r"((r)[24]),"r"((r)[25]),"r"((r)[26]),"r"((r)[27]),"r"((r)[28]),"r"((r)[29]),"r"((r)[30]),"r"((r)[31]) \
        : "memory")

#define TCGEN05_LD_X32(r, ta) \
    asm volatile("tcgen05.ld.sync.aligned.32x32b.x32.b32 " \
        "{%0,%1,%2,%3,%4,%5,%6,%7,%8,%9,%10,%11,%12,%13,%14,%15," \
        "%16,%17,%18,%19,%20,%21,%22,%23,%24,%25,%26,%27,%28,%29,%30,%31}, [%32];" \
        : "=r"((r)[0]),"=r"((r)[1]),"=r"((r)[2]),"=r"((r)[3]),"=r"((r)[4]),"=r"((r)[5]),"=r"((r)[6]),"=r"((r)[7]), \
          "=r"((r)[8]),"=r"((r)[9]),"=r"((r)[10]),"=r"((r)[11]),"=r"((r)[12]),"=r"((r)[13]),"=r"((r)[14]),"=r"((r)[15]), \
          "=r"((r)[16]),"=r"((r)[17]),"=r"((r)[18]),"=r"((r)[19]),"=r"((r)[20]),"=r"((r)[21]),"=r"((r)[22]),"=r"((r)[23]), \
          "=r"((r)[24]),"=r"((r)[25]),"=r"((r)[26]),"=r"((r)[27]),"=r"((r)[28]),"=r"((r)[29]),"=r"((r)[30]),"=r"((r)[31]) \
        : "r"(ta))

static __device__ __forceinline__ void mma_tf32_ts(uint32_t d_tmem, uint32_t a_tmem,
                                                   uint64_t b_desc, uint32_t idesc, bool en) {
    uint32_t e = en ? 1u : 0u;
    asm volatile(
        "{\n\t.reg .pred p;\n\tsetp.ne.u32 p, %4, 0;\n\t"
        "tcgen05.mma.cta_group::1.kind::tf32 [%0], [%1], %2, %3, {%5,%5,%5,%5}, p;\n\t}"
        :: "r"(d_tmem), "r"(a_tmem), "l"(b_desc), "r"(idesc), "r"(e), "r"(0u)
        : "memory");
}
#endif  // HAS_TCGEN05

__global__ void __launch_bounds__(THREADS, 2)
ml_kernel(const float* __restrict__ input,    // [KDIM, MDIM]
          const int*   __restrict__ regions,  // [CDIM]
          const float* __restrict__ wtab,     // [HEADS, KDIM, NDIM]
          const float* __restrict__ btab,     // [HEADS, NDIM]
          float*       __restrict__ out)      // [CDIM, MDIM, NDIM]
{
#if HAS_TCGEN05
    extern __shared__ unsigned char dsm_raw[];
    __shared__ uint64_t s_mbar[9];       // full[0..3], empty[0..3], done
    __shared__ uint32_t s_tmem_ptr;

    const int tid  = threadIdx.x;
    const int warp = tid >> 5;
    const int lane = tid & 31;

    const int b0 = blockIdx.x * BM;
    const int d0 = blockIdx.y * BN;
    const int c  = blockIdx.z;
    const int head = regions[c];
    const float* __restrict__ W = wtab + (size_t)head * (KDIM * NDIM);

    // 1024-align the B ring base (SW128 descriptor requirement)
    uint32_t bufu = (smem_u32(dsm_raw) + 1023u) & ~1023u;
    unsigned char* buf = dsm_raw + (bufu - smem_u32(dsm_raw));

    const uint32_t mb_full  = smem_u32(&s_mbar[0]);
    const uint32_t mb_empty = smem_u32(&s_mbar[4]);
    const uint32_t mb_done  = smem_u32(&s_mbar[8]);

    if (warp == 0) {
        TCGEN05_ALLOC(smem_u32(&s_tmem_ptr), TMEM_COLS_ALLOC);
        TCGEN05_RELINQ();
    }
    if (tid == 0) {
        #pragma unroll
        for (int b = 0; b < STAGES; b++) {
            MBAR_INIT(mb_full + b * 8, 8);   // 1 arrival per producer warp (4 A + 4 B)
            MBAR_INIT(mb_empty + b * 8, 1);  // tcgen05.commit
        }
        MBAR_INIT(mb_done, 1);
    }
    __syncthreads();
    uint32_t tmem_base;
    asm volatile("ld.shared.b32 %0, [%1];" : "=r"(tmem_base) : "r"(smem_u32(&s_tmem_ptr)));

    if (warp == 0) {
        // ================= MMA issuer =================
        for (int s = 0; s < NSTAGES; s++) {
            const int b = s & 3;
            MBAR_WAIT(mb_full + b * 8, (s >> 2) & 1);
            TCGEN05_FENCE_AFTER();
            if (elect1()) {
                const uint32_t abase = tmem_base + TM_A0 + b * 32;
                const uint32_t baddr = bufu + b * BSTG;
                #pragma unroll
                for (int ch = 0; ch < NCHUNK; ch++) {
                    const uint64_t bd0 = DESC_K | ((uint64_t)((baddr + ch * 4096) >> 4) & 0x3FFF);
                    #pragma unroll
                    for (int ks = 0; ks < KSTEPS; ks++)
                        mma_tf32_ts(tmem_base + TM_D + ch * 32, abase + ks * 8,
                                    bd0 + ks * 2, IDESC, !(s == 0 && ks == 0));
                }
                TCGEN05_COMMIT(mb_empty + b * 8);
            }
        }
        if (elect1()) TCGEN05_COMMIT(mb_done);
    } else if (warp <= 4) {
        // ================= A producers (warps 1-4) =================
        const int sub = warp & 3;                 // TMEM subpartition = m-rows sub*32..+31
        const float* ap0 = input + b0 + sub * 32 + lane;
        for (int s = 0; s < NSTAGES; s++) {
            const int b = s & 3;
            const float* ap = ap0 + (size_t)(s * BK) * MDIM;
            uint32_t a[32];
            #pragma unroll
            for (int j = 0; j < 32; j++) a[j] = tf32_bits(__ldg(ap + (size_t)j * MDIM));
            if (s >= STAGES) MBAR_WAIT(mb_empty + b * 8, ((s >> 2) - 1) & 1);
            TCGEN05_ST_X32(tmem_base + TM_A0 + b * 32 + ((uint32_t)sub << 21), a);
            TCGEN05_WAIT_ST();
            TCGEN05_FENCE_BEFORE();
            __syncwarp();
            if (elect1()) MBAR_ARRIVE(mb_full + b * 8);   // ONE arrival per warp
        }
    } else {
        // ================= B producers (warps 5-8) =================
        const int ch = warp - 5;                  // n-rows ch*32..+31
        const int nq = lane >> 2;                 // 0..7 n-quad
        const int cc = lane & 3;                  // 0..3 k-quad low
        const float* wb0 = W + d0 + ch * 32;
        for (int s = 0; s < NSTAGES; s++) {
            const int b = s & 3;
            const float* wbase = wb0 + (size_t)(s * BK) * NDIM;
            float4 v[2][4];
            #pragma unroll
            for (int p = 0; p < 2; p++) {
                const int kq = cc + 4 * p;
                #pragma unroll
                for (int r = 0; r < 4; r++)
                    v[p][r] = *(const float4*)(wbase + (size_t)(kq * 4 + r) * NDIM + nq * 4);
            }
            if (s >= STAGES) MBAR_WAIT(mb_empty + b * 8, ((s >> 2) - 1) & 1);
            unsigned char* bbase = buf + b * BSTG + ch * 4096;
            #pragma unroll
            for (int p = 0; p < 2; p++) {
                const int kq = cc + 4 * p;
                const float* f0 = (const float*)&v[p][0];
                const float* f1 = (const float*)&v[p][1];
                const float* f2 = (const float*)&v[p][2];
                const float* f3 = (const float*)&v[p][3];
                #pragma unroll
                for (int j = 0; j < 4; j++) {
                    uint4 t;
                    t.x = tf32_bits(f0[j]); t.y = tf32_bits(f1[j]);
                    t.z = tf32_bits(f2[j]); t.w = tf32_bits(f3[j]);
                    uint32_t off = SWZ((uint32_t)((nq * 4 + j) * 128 + kq * 16));
                    *(uint4*)(bbase + off) = t;
                }
            }
            FENCE_PROXY();
            __syncwarp();
            if (elect1()) MBAR_ARRIVE(mb_full + b * 8);   // ONE arrival per warp
        }
    }

    // ================= epilogue =================
    MBAR_WAIT(mb_done, 0);
    TCGEN05_FENCE_AFTER();

    float* outc = out + (size_t)c * (MDIM * NDIM);
    const float* brow = btab + (size_t)head * NDIM + d0;
    float* eb = (float*)buf;

    for (int h = 0; h < 2; h++) {
        __syncthreads();
        if (warp < 4) {
            uint32_t r[64];
            TCGEN05_LD_X32(r,      tmem_base + TM_D + h * 64);
            TCGEN05_LD_X32(r + 32, tmem_base + TM_D + h * 64 + 32);
            TCGEN05_WAIT_LD();
            float* rowp = eb + (warp * 32 + lane) * EPI_STRIDE;
            #pragma unroll
            for (int j = 0; j < 16; j++) {
                float4 v;
                v.x = __uint_as_float(r[j * 4 + 0]);
                v.y = __uint_as_float(r[j * 4 + 1]);
                v.z = __uint_as_float(r[j * 4 + 2]);
                v.w = __uint_as_float(r[j * 4 + 3]);
                *(float4*)(rowp + j * 4) = v;
            }
        }
        __syncthreads();
        if (tid < 256) {
            #pragma unroll
            for (int it = 0; it < 8; it++) {
                const int e = it * 256 + tid;
                const int m = e >> 4;
                const int jj = (e & 15) << 2;
                float4 v = *(float4*)(eb + m * EPI_STRIDE + jj);
                float4 bv = *(const float4*)(brow + h * 64 + jj);
                v.x += bv.x; v.y += bv.y; v.z += bv.z; v.w += bv.w;
                *(float4*)(outc + (size_t)(b0 + m) * NDIM + d0 + h * 64 + jj) = v;
            }
        }
    }

    __syncthreads();
    if (warp == 0) TCGEN05_DEALLOC(tmem_base, TMEM_COLS_ALLOC);

#else
    // ===== trivial correct fallback (never runs when arch pass exists) =====
    const int b0 = blockIdx.x * BM;
    const int d0 = blockIdx.y * BN;
    const int c  = blockIdx.z;
    const int head = regions[c];
    const float* Wp = wtab + (size_t)head * (KDIM * NDIM);
    float* outc = out + (size_t)c * (MDIM * NDIM);
    for (int e = threadIdx.x; e < BM * BN; e += blockDim.x) {
        const int m = b0 + (e >> 7);
        const int n = d0 + (e & 127);
        float acc = btab[(size_t)head * NDIM + n];
        for (int k = 0; k < KDIM; k++)
            acc += input[(size_t)k * MDIM + m] * Wp[(size_t)k * NDIM + n];
        outc[(size_t)m * NDIM + n] = acc;
    }
#endif
}

extern "C" void kernel_launch(void* const* d_in, const int* in_sizes, int n_in,
                              void* d_out, int out_size) {
    const float* input   = (const float*)d_in[0];
    const int*   regions = (const int*)  d_in[1];
    const float* wtab    = (const float*)d_in[2];
    const float* btab    = (const float*)d_in[3];
    float* out = (float*)d_out;

    cudaFuncSetAttribute(ml_kernel, cudaFuncAttributeMaxDynamicSharedMemorySize, SMEM_DYN);
    dim3 grid(MDIM / BM, NDIM / BN, CDIM);  // x fastest: m-tiles share W d-slice in L2
    ml_kernel<<<grid, THREADS, SMEM_DYN>>>(input, regions, wtab, btab, out);
}